// round 5
// baseline (speedup 1.0000x reference)
#include <cuda_runtime.h>
#include <cstdint>

// Shapes fixed by the reference
#define NB   4
#define DB   8
#define CB   3
#define RB   4
#define KK   5
#define HH   128
#define WW   128
#define HWSZ (HH * WW)

#define TH_   2                       // output rows per block
#define NSTG  3                       // ring stages
#define NCHUNK 5                      // chunks per tile (one per i)
// chunk = 20 planes (4r x 5j) x TH_ rows x 128 w x 4B = 20 KB
#define PLANE_BYTES  (TH_ * WW * 4)          // 1024
#define CHUNK_BYTES  (RB * KK * PLANE_BYTES) // 20480
#define RING_BYTES   (NSTG * CHUNK_BYTES)    // 61440

// burst tile: 3 ch x (TH_+4) rows x 132 cols
#define BROWS (TH_ + 4)               // 6
#define BCOLS (WW + 4)                // 132
#define BURST_FLOATS (CB * BROWS * BCOLS)    // 2376
#define BURST_BYTES  (BURST_FLOATS * 4)      // 9504

#define SMEM_MBAR   0                 // 3 x 8B barriers
#define SMEM_BURST  64
#define SMEM_RING   (SMEM_BURST + BURST_BYTES)   // 9568 (16B aligned)
#define SMEM_TOTAL  (SMEM_RING + RING_BYTES)     // 71008

__device__ __forceinline__ uint32_t smem_u32(const void* p) {
    return (uint32_t)__cvta_generic_to_shared(p);
}
__device__ __forceinline__ void mbar_init(uint32_t a, uint32_t cnt) {
    asm volatile("mbarrier.init.shared.b64 [%0], %1;" :: "r"(a), "r"(cnt) : "memory");
}
__device__ __forceinline__ void mbar_expect_tx(uint32_t a, uint32_t bytes) {
    asm volatile("mbarrier.arrive.expect_tx.shared.b64 _, [%0], %1;"
                 :: "r"(a), "r"(bytes) : "memory");
}
__device__ __forceinline__ void bulk_g2s(uint32_t dst, const void* src, uint32_t bytes,
                                         uint32_t mbar) {
    asm volatile("cp.async.bulk.shared::cluster.global.mbarrier::complete_tx::bytes "
                 "[%0], [%1], %2, [%3];"
                 :: "r"(dst), "l"(src), "r"(bytes), "r"(mbar) : "memory");
}
__device__ __forceinline__ void fence_proxy_async_cta() {
    asm volatile("fence.proxy.async.shared::cta;" ::: "memory");
}
__device__ __forceinline__ void mbar_wait_parity(uint32_t a, uint32_t phase) {
    asm volatile(
        "{\n\t"
        ".reg .pred P1;\n\t"
        "WAIT_LOOP_%=:\n\t"
        "mbarrier.try_wait.parity.acquire.cta.shared::cta.b64 P1, [%0], %1, 0x989680;\n\t"
        "@P1 bra.uni WAIT_DONE_%=;\n\t"
        "bra.uni WAIT_LOOP_%=;\n\t"
        "WAIT_DONE_%=:\n\t"
        "}"
        :: "r"(a), "r"(phase) : "memory");
}

__global__ __launch_bounds__(256, 3)
void adaptive_conv_ps_v5(const float* __restrict__ burst,
                         const float* __restrict__ kernels,
                         float* __restrict__ out)
{
    extern __shared__ char smem[];
    float* s_burst = reinterpret_cast<float*>(smem + SMEM_BURST);
    const uint32_t smem_base = smem_u32(smem);
    const uint32_t mbar0 = smem_base + SMEM_MBAR;       // full[s] at mbar0 + 8s
    const uint32_t ring  = smem_base + SMEM_RING;

    const int h0 = blockIdx.x * TH_;          // 0..126
    const int nd = blockIdx.y;                // 0..31
    const int x  = threadIdx.x;               // 0..63 -> pixels (2x, 2x+1)
    const int si = threadIdx.y;               // 0..1
    const int z  = threadIdx.z;               // 0..1 (row)
    const int tid = x + 64 * si + 128 * z;

    const char* kbase = reinterpret_cast<const char*>(kernels)
                      + ((size_t)nd * (RB * KK * KK)) * (HWSZ * 4)
                      + (size_t)h0 * (WW * 4);

    // ---- init barriers + kick off first NSTG chunk prefetches (thread 0) ----
    if (tid == 0) {
        #pragma unroll
        for (int s = 0; s < NSTG; s++) mbar_init(mbar0 + 8 * s, 1);
        fence_proxy_async_cta();
        #pragma unroll
        for (int c = 0; c < NSTG; c++) {
            const uint32_t bar = mbar0 + 8 * c;
            mbar_expect_tx(bar, CHUNK_BYTES);
            #pragma unroll
            for (int r = 0; r < RB; r++)
                #pragma unroll
                for (int j = 0; j < KK; j++)
                    bulk_g2s(ring + c * CHUNK_BYTES + (r * KK + j) * PLANE_BYTES,
                             kbase + (size_t)(r * 25 + c * KK + j) * (HWSZ * 4),
                             PLANE_BYTES, bar);
        }
    }

    // ---- stage burst tile (rows h0-2..h0+3, cols -2..129, zero-pad) ----
    const float* bptr = burst + (size_t)nd * CB * HWSZ;
    for (int idx = tid; idx < BURST_FLOATS; idx += 256) {
        int c   = idx / (BROWS * BCOLS);
        int rem = idx - c * (BROWS * BCOLS);
        int row = rem / BCOLS;
        int col = rem - row * BCOLS;
        int gh  = h0 + row - 2;
        int gw  = col - 2;
        float v = 0.0f;
        if (gh >= 0 && gh < HH && gw >= 0 && gw < WW)
            v = bptr[c * HWSZ + gh * WW + gw];
        s_burst[idx] = v;
    }
    __syncthreads();

    float acc[CB][2][2];   // [channel][sj = r_local][pixel]
    #pragma unroll
    for (int c = 0; c < CB; c++)
        #pragma unroll
        for (int a = 0; a < 2; a++) { acc[c][a][0] = 0.f; acc[c][a][1] = 0.f; }

    // ---- main loop over i-row chunks ----
    #pragma unroll
    for (int c = 0; c < NCHUNK; c++) {
        const int slot = (c < NSTG) ? c : c - NSTG;
        mbar_wait_parity(mbar0 + 8 * slot, (c >= NSTG) ? 1u : 0u);

        // burst window for this tap row: cols 2x .. 2x+5, row z+c (halo included)
        float bw[CB][6];
        #pragma unroll
        for (int ch = 0; ch < CB; ch++) {
            const float* brow = s_burst + (ch * BROWS + (z + c)) * BCOLS + 2 * x;
            #pragma unroll
            for (int q = 0; q < 3; q++) {
                float2 t = *reinterpret_cast<const float2*>(brow + 2 * q);
                bw[ch][2 * q] = t.x; bw[ch][2 * q + 1] = t.y;
            }
        }

        const uint32_t kslot = ring + slot * CHUNK_BYTES + z * (WW * 4) + x * 8;
        #pragma unroll
        for (int j = 0; j < KK; j++) {
            float2 k0, k1;   // r = 2si, 2si+1 at pixels (2x, 2x+1)
            asm volatile("ld.shared.v2.f32 {%0,%1}, [%2];"
                         : "=f"(k0.x), "=f"(k0.y)
                         : "r"(kslot + (uint32_t)((10 * si + j) * PLANE_BYTES)));
            asm volatile("ld.shared.v2.f32 {%0,%1}, [%2];"
                         : "=f"(k1.x), "=f"(k1.y)
                         : "r"(kslot + (uint32_t)((10 * si + 5 + j) * PLANE_BYTES)));
            #pragma unroll
            for (int ch = 0; ch < CB; ch++) {
                acc[ch][0][0] = fmaf(k0.x, bw[ch][j + 0], acc[ch][0][0]);
                acc[ch][0][1] = fmaf(k0.y, bw[ch][j + 1], acc[ch][0][1]);
                acc[ch][1][0] = fmaf(k1.x, bw[ch][j + 0], acc[ch][1][0]);
                acc[ch][1][1] = fmaf(k1.y, bw[ch][j + 1], acc[ch][1][1]);
            }
        }

        __syncthreads();                       // all consumers done with this slot
        if (tid == 0 && c + NSTG < NCHUNK) {   // refill freed slot with chunk c+3
            const int cn = c + NSTG;
            const uint32_t bar = mbar0 + 8 * slot;
            mbar_expect_tx(bar, CHUNK_BYTES);
            #pragma unroll
            for (int r = 0; r < RB; r++)
                #pragma unroll
                for (int j = 0; j < KK; j++)
                    bulk_g2s(ring + slot * CHUNK_BYTES + (r * KK + j) * PLANE_BYTES,
                             kbase + (size_t)(r * 25 + cn * KK + j) * (HWSZ * 4),
                             PLANE_BYTES, bar);
        }
    }

    // ---- fused pixel shuffle epilogue ----
    // out (nd, c, 2H, 2W); thread owns row 2(h0+z)+si, cols 4x..4x+3
    float4* o4 = reinterpret_cast<float4*>(out);
    const int orow_in = 2 * (h0 + z) + si;
    #pragma unroll
    for (int ch = 0; ch < CB; ch++) {
        const size_t row = (size_t)(nd * CB + ch) * (2 * HH) + orow_in;
        __stcs(&o4[row * (2 * WW / 4) + x],
               make_float4(acc[ch][0][0], acc[ch][1][0], acc[ch][0][1], acc[ch][1][1]));
    }
}

extern "C" void kernel_launch(void* const* d_in, const int* in_sizes, int n_in,
                              void* d_out, int out_size)
{
    const float* burst   = (const float*)d_in[0];   // (4,8,3,128,128)
    const float* kernels = (const float*)d_in[1];   // (4,8,4,5,5,128,128)
    float* out = (float*)d_out;                     // (4,8,3,256,256)

    cudaFuncSetAttribute(adaptive_conv_ps_v5,
                         cudaFuncAttributeMaxDynamicSharedMemorySize, SMEM_TOTAL);

    dim3 block(64, 2, 2);                           // 256 threads
    dim3 grid(HH / TH_, NB * DB, 1);                // (64, 32) = 2048 blocks
    adaptive_conv_ps_v5<<<grid, block, SMEM_TOTAL>>>(burst, kernels, out);
}

// round 6
// speedup vs baseline: 1.2147x; 1.2147x over previous
#include <cuda_runtime.h>

// Shapes fixed by the reference
#define NB   4
#define DB   8
#define CB   3
#define RB   4
#define KK   5
#define HH   128
#define WW   128
#define HWSZ (HH * WW)
#define TW   16                     // tile width (pixels)
#define TH   4                      // tile height
#define SH_  (TH + 4)               // 8
#define SW_  (TW + 4)               // 20

// Block (16, 4, 4): x = pixel col, y = r (si*2+sj), z = row. 256 threads.
// Warp = 16 px x 2 r (sj pair, same si) -> shfl_xor(16) reunites sj pairs.
__global__ __launch_bounds__(256, 8)
void adaptive_conv_ps_v6(const float* __restrict__ burst,
                         const float* __restrict__ kernels,
                         float* __restrict__ out)
{
    __shared__ float s[CB][SH_][SW_];

    const int nd = blockIdx.z;                 // 0..31
    const int h0 = blockIdx.y * TH;
    const int w0 = blockIdx.x * TW;
    const int x  = threadIdx.x;                // 0..15
    const int r  = threadIdx.y;                // 0..3
    const int z  = threadIdx.z;                // 0..3
    const int tid = x + 16 * r + 64 * z;

    // ---- stage burst tile (3 ch, halo 2, zero-pad OOB): 480 elems ----
    const float* bptr = burst + (size_t)nd * CB * HWSZ;
    #pragma unroll
    for (int k = 0; k < 2; k++) {
        int idx = tid + k * 256;
        if (idx < CB * SH_ * SW_) {
            int c   = idx / (SH_ * SW_);
            int rem = idx - c * (SH_ * SW_);
            int row = rem / SW_;
            int col = rem - row * SW_;
            int gh  = h0 + row - 2;
            int gw  = w0 + col - 2;
            float v = 0.0f;
            if (gh >= 0 && gh < HH && gw >= 0 && gw < WW)
                v = bptr[c * HWSZ + gh * WW + gw];
            s[c][row][col] = v;
        }
    }
    __syncthreads();

    const int h = h0 + z;
    const int w = w0 + x;

    float a0 = 0.f, a1 = 0.f, a2 = 0.f;

    // kernels: (nd, r, i, j, h, w); this thread streams its own r's 25 planes
    const float* kp = kernels
                    + ((size_t)nd * (RB * KK * KK) + (size_t)r * (KK * KK)) * HWSZ
                    + (size_t)h * WW + w;

    #pragma unroll
    for (int i = 0; i < KK; i++) {
        #pragma unroll
        for (int j = 0; j < KK; j++) {
            const float kv = __ldcs(kp + (size_t)(i * KK + j) * HWSZ);
            a0 = fmaf(kv, s[0][z + i][x + j], a0);
            a1 = fmaf(kv, s[1][z + i][x + j], a1);
            a2 = fmaf(kv, s[2][z + i][x + j], a2);
        }
    }

    // ---- fused pixel shuffle epilogue ----
    // r = 2*si + sj. Warp: lanes 0-15 hold sj=0, lanes 16-31 hold sj=1 (same si, same px).
    const int si = r >> 1;
    const unsigned lane = tid & 31u;
    const float p0 = __shfl_xor_sync(0xffffffffu, a0, 16);
    const float p1 = __shfl_xor_sync(0xffffffffu, a1, 16);
    const float p2 = __shfl_xor_sync(0xffffffffu, a2, 16);

    if (lane < 16) {   // sj==0 lanes assemble (sj0, sj1) pairs -> coalesced float2
        float2* o2 = reinterpret_cast<float2*>(out);
        const size_t rowb = (size_t)(nd * CB) * (2 * HH) + (2 * h + si);
        __stcs(&o2[(rowb + 0 * (2 * HH)) * WW + w], make_float2(a0, p0));
        __stcs(&o2[(rowb + 1 * (2 * HH)) * WW + w], make_float2(a1, p1));
        __stcs(&o2[(rowb + 2 * (2 * HH)) * WW + w], make_float2(a2, p2));
    }
}

extern "C" void kernel_launch(void* const* d_in, const int* in_sizes, int n_in,
                              void* d_out, int out_size)
{
    const float* burst   = (const float*)d_in[0];   // (4,8,3,128,128)
    const float* kernels = (const float*)d_in[1];   // (4,8,4,5,5,128,128)
    float* out = (float*)d_out;                     // (4,8,3,256,256)

    dim3 block(16, 4, 4);                           // 256 threads
    dim3 grid(WW / TW, HH / TH, NB * DB);           // (8, 32, 32) = 8192 blocks
    adaptive_conv_ps_v6<<<grid, block>>>(burst, kernels, out);
}